// round 2
// baseline (speedup 1.0000x reference)
#include <cuda_runtime.h>

#define NN   50000
#define EE   800000
#define FIN  128
#define HH   64
#define NEXP 3
#define GG   64
#define NCLS 3
#define BNEPS 1e-5f

// ---------------- static device scratch (no allocations) ----------------
__device__ int      g_deg_cnt[NN];
__device__ int      g_fill_cnt[NN];
__device__ int      g_row_ptr[NN + 1];
__device__ int      g_csr_src[EE];
__device__ float    g_disq[NN];
__device__ float    g_dinv[NN];
__device__ float    g_gate[NN * NEXP];
__device__ __align__(16) float g_xp[NN * FIN];
__device__ __align__(16) float g_h1[NN * HH];
__device__ __align__(16) float g_t[NN * HH];
__device__ __align__(16) float g_o2[NN * HH];
__device__ float    g_bn1_sum[HH], g_bn1_sq[HH];
__device__ float    g_bn2_sum[HH], g_bn2_sq[HH];
__device__ __align__(16) float g_sc1[HH];
__device__ __align__(16) float g_sh1[HH];
__device__ __align__(16) float g_sc2[HH];
__device__ __align__(16) float g_sh2[HH];
__device__ float    g_pool_sum[GG * HH];
__device__ unsigned g_pool_max[GG * HH];
__device__ int      g_pool_cnt[GG];

// ---------------- zero scratch ----------------
__global__ void k_zero() {
    int i = blockIdx.x * blockDim.x + threadIdx.x;
    if (i < NN) { g_deg_cnt[i] = 0; g_fill_cnt[i] = 0; }
    if (i < HH) { g_bn1_sum[i] = 0.f; g_bn1_sq[i] = 0.f; g_bn2_sum[i] = 0.f; g_bn2_sq[i] = 0.f; }
    if (i < GG * HH) { g_pool_sum[i] = 0.f; g_pool_max[i] = 0u; }
    if (i < GG) g_pool_cnt[i] = 0;
}

// ---------------- in-degree histogram ----------------
__global__ void k_hist(const int* __restrict__ dst) {
    int e = blockIdx.x * blockDim.x + threadIdx.x;
    if (e < EE) atomicAdd(&g_deg_cnt[dst[e]], 1);
}

// ---------------- exclusive scan (row_ptr) + deg_isqrt/deg_inv ----------------
__global__ void k_scan() {
    __shared__ int wsum[32];
    __shared__ int carry_s;
    const int tid = threadIdx.x, lane = tid & 31, wid = tid >> 5;
    if (tid == 0) carry_s = 0;
    __syncthreads();
    for (int base = 0; base < NN; base += 1024) {
        int i = base + tid;
        int v = (i < NN) ? g_deg_cnt[i] : 0;
        int x = v;
#pragma unroll
        for (int o = 1; o < 32; o <<= 1) {
            int y = __shfl_up_sync(0xffffffffu, x, o);
            if (lane >= o) x += y;
        }
        if (lane == 31) wsum[wid] = x;
        __syncthreads();
        if (wid == 0) {
            int w = wsum[lane];
#pragma unroll
            for (int o = 1; o < 32; o <<= 1) {
                int y = __shfl_up_sync(0xffffffffu, w, o);
                if (lane >= o) w += y;
            }
            wsum[lane] = w;  // inclusive warp sums
        }
        __syncthreads();
        int woff = (wid == 0) ? 0 : wsum[wid - 1];
        int incl = x + woff;
        int carry = carry_s;
        if (i < NN) {
            g_row_ptr[i] = carry + incl - v;
            float dg = (float)(v + 1);
            g_disq[i] = rsqrtf(dg);
            g_dinv[i] = 1.0f / dg;
        }
        __syncthreads();
        if (tid == 1023) carry_s = carry + incl;
        __syncthreads();
    }
    if (tid == 0) g_row_ptr[NN] = carry_s;
}

// ---------------- CSR fill ----------------
__global__ void k_fill(const int* __restrict__ src, const int* __restrict__ dst) {
    int e = blockIdx.x * blockDim.x + threadIdx.x;
    if (e < EE) {
        int d = dst[e];
        int pos = atomicAdd(&g_fill_cnt[d], 1);
        g_csr_src[g_row_ptr[d] + pos] = src[e];
    }
}

// ---------------- gate MLP: softmax(relu(x@W1+b1)@W2+b2) ----------------
__global__ void k_gate(const float* __restrict__ x, const float* __restrict__ W1,
                       const float* __restrict__ b1, const float* __restrict__ W2,
                       const float* __restrict__ b2g) {
    __shared__ float W1s[FIN * 32];
    __shared__ float W2s[32 * 3];
    __shared__ float b1s[32];
    __shared__ float b2s[3];
    __shared__ __align__(16) float xs[8][4][FIN];
    int tid = threadIdx.x;
    for (int i = tid; i < FIN * 32; i += blockDim.x) W1s[i] = W1[i];
    if (tid < 96) W2s[tid] = W2[tid];
    if (tid < 32) b1s[tid] = b1[tid];
    if (tid < 3)  b2s[tid] = b2g[tid];
    __syncthreads();
    int w = tid >> 5, lane = tid & 31;
    int warps_total = gridDim.x * 8;
    for (int n0 = (blockIdx.x * 8 + w) * 4; n0 < NN; n0 += warps_total * 4) {
        int nmax = min(4, NN - n0);
        for (int i = 0; i < nmax; i++) {
            float4 v = ((const float4*)(x + (size_t)(n0 + i) * FIN))[lane];
            ((float4*)&xs[w][i][0])[lane] = v;
        }
        __syncwarp();
        float acc[4];
#pragma unroll
        for (int i = 0; i < 4; i++) acc[i] = b1s[lane];
        for (int f = 0; f < FIN; f += 4) {
            float4 xv[4];
#pragma unroll
            for (int i = 0; i < 4; i++) xv[i] = *((const float4*)&xs[w][i][f]);
#pragma unroll
            for (int ff = 0; ff < 4; ff++) {
                float wv = W1s[(f + ff) * 32 + lane];
#pragma unroll
                for (int i = 0; i < 4; i++) {
                    float xc = (ff == 0) ? xv[i].x : (ff == 1) ? xv[i].y : (ff == 2) ? xv[i].z : xv[i].w;
                    acc[i] += xc * wv;
                }
            }
        }
        for (int i = 0; i < nmax; i++) {
            float hid = fmaxf(acc[i], 0.f);
            float p0 = hid * W2s[lane * 3 + 0];
            float p1 = hid * W2s[lane * 3 + 1];
            float p2 = hid * W2s[lane * 3 + 2];
#pragma unroll
            for (int o = 16; o > 0; o >>= 1) {
                p0 += __shfl_down_sync(0xffffffffu, p0, o);
                p1 += __shfl_down_sync(0xffffffffu, p1, o);
                p2 += __shfl_down_sync(0xffffffffu, p2, o);
            }
            if (lane == 0) {
                p0 += b2s[0]; p1 += b2s[1]; p2 += b2s[2];
                float m = fmaxf(p0, fmaxf(p1, p2));
                float e0 = __expf(p0 - m), e1 = __expf(p1 - m), e2 = __expf(p2 - m);
                float inv = 1.f / (e0 + e1 + e2);
                int n = n0 + i;
                g_gate[n * 3 + 0] = e0 * inv;
                g_gate[n * 3 + 1] = e1 * inv;
                g_gate[n * 3 + 2] = e2 * inv;
            }
        }
        __syncwarp();
    }
}

// ---------------- prop1: xp = GCN-prop(x), F=128, warp per dst node ----------------
__global__ void k_prop1(const float* __restrict__ x) {
    int w = (blockIdx.x * blockDim.x + threadIdx.x) >> 5;
    int lane = threadIdx.x & 31;
    if (w >= NN) return;
    int n = w;
    const float4* x4 = (const float4*)x;
    float4 acc = make_float4(0.f, 0.f, 0.f, 0.f);
    int j0 = g_row_ptr[n], j1 = g_row_ptr[n + 1];
    for (int j = j0; j < j1; j++) {
        int s = __ldg(&g_csr_src[j]);
        float wv = __ldg(&g_disq[s]);
        float4 v = __ldg(&x4[(size_t)s * 32 + lane]);
        acc.x += wv * v.x; acc.y += wv * v.y; acc.z += wv * v.z; acc.w += wv * v.w;
    }
    float dq = g_disq[n], di = g_dinv[n];
    float4 sv = x4[(size_t)n * 32 + lane];
    float4 o;
    o.x = acc.x * dq + sv.x * di;
    o.y = acc.y * dq + sv.y * di;
    o.z = acc.z * dq + sv.z * di;
    o.w = acc.w * dq + sv.w * di;
    ((float4*)g_xp)[(size_t)n * 32 + lane] = o;
}

// ---------------- expert GEMM + bias + gate combine + BN1 partial stats ----------------
// h1[n,h] = sum_e gate[n,e] * ( (xp @ W_e)[n,h] + b_exp[e,h] )
__global__ void __launch_bounds__(512, 1) k_expert(const float* __restrict__ W_exp,
                                                   const float* __restrict__ b_exp) {
    extern __shared__ __align__(16) float sm[];
    float* Ws = sm;                 // [FIN][192]  col = e*64+h
    float* be = sm + FIN * 192;     // [192]
    float* xs = sm + FIN * 192 + 192;  // [16 warps][4 nodes][FIN]
    int tid = threadIdx.x;
    for (int idx = tid; idx < FIN * 192; idx += blockDim.x) {
        int f = idx / 192, c = idx % 192;
        int e = c >> 6, h = c & 63;
        Ws[idx] = W_exp[((size_t)e * FIN + f) * 64 + h];
    }
    if (tid < 192) be[tid] = b_exp[tid];  // [NE,H] row-major == e*64+h
    __syncthreads();
    int w = tid >> 5, lane = tid & 31;
    float* xw = xs + w * 4 * FIN;
    float bs0 = 0.f, bq0 = 0.f, bs1 = 0.f, bq1 = 0.f;
    int warps_total = gridDim.x * (blockDim.x >> 5);
    for (int n0 = (blockIdx.x * (blockDim.x >> 5) + w) * 4; n0 < NN; n0 += warps_total * 4) {
        int nmax = min(4, NN - n0);
        for (int i = 0; i < nmax; i++) {
            float4 v = ((const float4*)(g_xp + (size_t)(n0 + i) * FIN))[lane];
            ((float4*)(xw + i * FIN))[lane] = v;
        }
        __syncwarp();
        float acc[4][6];
#pragma unroll
        for (int i = 0; i < 4; i++)
#pragma unroll
            for (int k = 0; k < 6; k++) acc[i][k] = 0.f;
        for (int f = 0; f < FIN; f += 4) {
            float4 xv[4];
#pragma unroll
            for (int i = 0; i < 4; i++) xv[i] = *((const float4*)(xw + i * FIN + f));
#pragma unroll
            for (int ff = 0; ff < 4; ff++) {
                const float* wrow = Ws + (f + ff) * 192;
                float w0 = wrow[lane];
                float w1 = wrow[lane + 32];
                float w2 = wrow[lane + 64];
                float w3 = wrow[lane + 96];
                float w4 = wrow[lane + 128];
                float w5 = wrow[lane + 160];
#pragma unroll
                for (int i = 0; i < 4; i++) {
                    float xc = (ff == 0) ? xv[i].x : (ff == 1) ? xv[i].y : (ff == 2) ? xv[i].z : xv[i].w;
                    acc[i][0] += xc * w0; acc[i][1] += xc * w1;
                    acc[i][2] += xc * w2; acc[i][3] += xc * w3;
                    acc[i][4] += xc * w4; acc[i][5] += xc * w5;
                }
            }
        }
        for (int i = 0; i < nmax; i++) {
            int n = n0 + i;
            float g0 = g_gate[n * 3 + 0], g1 = g_gate[n * 3 + 1], g2 = g_gate[n * 3 + 2];
            // lane holds cols lane+32k: (e,h) = (0,l),(0,l+32),(1,l),(1,l+32),(2,l),(2,l+32)
            float oa = g0 * (acc[i][0] + be[lane]) + g1 * (acc[i][2] + be[64 + lane]) + g2 * (acc[i][4] + be[128 + lane]);
            float ob = g0 * (acc[i][1] + be[lane + 32]) + g1 * (acc[i][3] + be[96 + lane]) + g2 * (acc[i][5] + be[160 + lane]);
            g_h1[(size_t)n * 64 + lane] = oa;
            g_h1[(size_t)n * 64 + lane + 32] = ob;
            bs0 += oa; bq0 += oa * oa; bs1 += ob; bq1 += ob * ob;
        }
        __syncwarp();
    }
    atomicAdd(&g_bn1_sum[lane], bs0);
    atomicAdd(&g_bn1_sq[lane], bq0);
    atomicAdd(&g_bn1_sum[lane + 32], bs1);
    atomicAdd(&g_bn1_sq[lane + 32], bq1);
}

// ---------------- BN finalize: fold (mu, var, gamma, beta) into scale/shift ----------------
__global__ void k_bnfin1(const float* __restrict__ gam, const float* __restrict__ bet) {
    int i = threadIdx.x;
    if (i < HH) {
        float mu = g_bn1_sum[i] / (float)NN;
        float var = g_bn1_sq[i] / (float)NN - mu * mu;
        float sc = rsqrtf(var + BNEPS) * gam[i];
        g_sc1[i] = sc;
        g_sh1[i] = bet[i] - mu * sc;
    }
}
__global__ void k_bnfin2(const float* __restrict__ gam, const float* __restrict__ bet) {
    int i = threadIdx.x;
    if (i < HH) {
        float mu = g_bn2_sum[i] / (float)NN;
        float var = g_bn2_sq[i] / (float)NN - mu * mu;
        float sc = rsqrtf(var + BNEPS) * gam[i];
        g_sc2[i] = sc;
        g_sh2[i] = bet[i] - mu * sc;
    }
}

// ---------------- BN1 + ReLU + @W2 ----------------
__global__ void k_bnw2(const float* __restrict__ W2) {
    __shared__ float W2s[HH * HH];
    __shared__ __align__(16) float scs[HH];
    __shared__ __align__(16) float shs[HH];
    __shared__ __align__(16) float xs[8][4][HH];
    int tid = threadIdx.x;
    for (int i = tid; i < HH * HH; i += blockDim.x) W2s[i] = W2[i];
    if (tid < HH) { scs[tid] = g_sc1[tid]; shs[tid] = g_sh1[tid]; }
    __syncthreads();
    int w = tid >> 5, lane = tid & 31;
    int warps_total = gridDim.x * 8;
    for (int n0 = (blockIdx.x * 8 + w) * 4; n0 < NN; n0 += warps_total * 4) {
        int nmax = min(4, NN - n0);
        float2 sc = ((const float2*)scs)[lane];
        float2 sh = ((const float2*)shs)[lane];
        for (int i = 0; i < nmax; i++) {
            float2 v = ((const float2*)(g_h1 + (size_t)(n0 + i) * HH))[lane];
            float2 o;
            o.x = fmaxf(v.x * sc.x + sh.x, 0.f);
            o.y = fmaxf(v.y * sc.y + sh.y, 0.f);
            ((float2*)&xs[w][i][0])[lane] = o;
        }
        __syncwarp();
        float acc[4][2];
#pragma unroll
        for (int i = 0; i < 4; i++) { acc[i][0] = 0.f; acc[i][1] = 0.f; }
        for (int f = 0; f < HH; f += 4) {
            float4 xv[4];
#pragma unroll
            for (int i = 0; i < 4; i++) xv[i] = *((const float4*)&xs[w][i][f]);
#pragma unroll
            for (int ff = 0; ff < 4; ff++) {
                float w0 = W2s[(f + ff) * 64 + lane];
                float w1 = W2s[(f + ff) * 64 + lane + 32];
#pragma unroll
                for (int i = 0; i < 4; i++) {
                    float xc = (ff == 0) ? xv[i].x : (ff == 1) ? xv[i].y : (ff == 2) ? xv[i].z : xv[i].w;
                    acc[i][0] += xc * w0;
                    acc[i][1] += xc * w1;
                }
            }
        }
        for (int i = 0; i < nmax; i++) {
            g_t[(size_t)(n0 + i) * 64 + lane] = acc[i][0];
            g_t[(size_t)(n0 + i) * 64 + lane + 32] = acc[i][1];
        }
        __syncwarp();
    }
}

// ---------------- prop2 (+b2) + BN2 partial stats ----------------
__global__ void k_prop2(const float* __restrict__ b2) {
    int lane = threadIdx.x & 31;
    int w = threadIdx.x >> 5;
    int warps_total = gridDim.x * (blockDim.x >> 5);
    const float2* t2 = (const float2*)g_t;
    float bsx = 0.f, bqx = 0.f, bsy = 0.f, bqy = 0.f;
    float2 bv;
    bv.x = b2[2 * lane];
    bv.y = b2[2 * lane + 1];
    for (int n = blockIdx.x * (blockDim.x >> 5) + w; n < NN; n += warps_total) {
        float2 acc = make_float2(0.f, 0.f);
        int j0 = g_row_ptr[n], j1 = g_row_ptr[n + 1];
        for (int j = j0; j < j1; j++) {
            int s = __ldg(&g_csr_src[j]);
            float wv = __ldg(&g_disq[s]);
            float2 v = __ldg(&t2[(size_t)s * 32 + lane]);
            acc.x += wv * v.x;
            acc.y += wv * v.y;
        }
        float dq = g_disq[n], di = g_dinv[n];
        float2 sv = t2[(size_t)n * 32 + lane];
        float2 o;
        o.x = acc.x * dq + sv.x * di + bv.x;
        o.y = acc.y * dq + sv.y * di + bv.y;
        ((float2*)g_o2)[(size_t)n * 32 + lane] = o;
        bsx += o.x; bqx += o.x * o.x;
        bsy += o.y; bqy += o.y * o.y;
    }
    atomicAdd(&g_bn2_sum[2 * lane], bsx);
    atomicAdd(&g_bn2_sq[2 * lane], bqx);
    atomicAdd(&g_bn2_sum[2 * lane + 1], bsy);
    atomicAdd(&g_bn2_sq[2 * lane + 1], bqy);
}

// ---------------- BN2 + ReLU + segment pooling (sum/max/count) ----------------
__global__ void k_pool(const int* __restrict__ batch) {
    __shared__ float    ssum[GG * HH];
    __shared__ unsigned smax[GG * HH];
    __shared__ int      scnt[GG];
    int tid = threadIdx.x;
    int base = blockIdx.x * 512;
    int lastn = min(base + 511, NN - 1);
    int gmin = batch[base], gmax = batch[lastn];
    int ngr = gmax - gmin + 1;
    for (int i = tid; i < ngr * HH; i += blockDim.x) { ssum[i] = 0.f; smax[i] = 0u; }
    if (tid < ngr) scnt[tid] = 0;
    __syncthreads();
    int f = tid & 63, r = tid >> 6;
    float sc = g_sc2[f], sh = g_sh2[f];
    int curg = -1; float ls = 0.f, lm = 0.f; int lc = 0;
    for (int i = r; i < 512; i += 4) {
        int n = base + i;
        if (n >= NN) break;
        int g = batch[n];
        float v = fmaxf(g_o2[(size_t)n * 64 + f] * sc + sh, 0.f);
        if (g != curg) {
            if (curg >= 0) {
                atomicAdd(&ssum[(curg - gmin) * 64 + f], ls);
                atomicMax(&smax[(curg - gmin) * 64 + f], __float_as_uint(lm));
                if (f == 0) atomicAdd(&scnt[curg - gmin], lc);
            }
            curg = g; ls = v; lm = v; lc = 1;
        } else {
            ls += v; lm = fmaxf(lm, v); lc++;
        }
    }
    if (curg >= 0) {
        atomicAdd(&ssum[(curg - gmin) * 64 + f], ls);
        atomicMax(&smax[(curg - gmin) * 64 + f], __float_as_uint(lm));
        if (f == 0) atomicAdd(&scnt[curg - gmin], lc);
    }
    __syncthreads();
    for (int i = tid; i < ngr * HH; i += blockDim.x) {
        int lg = i >> 6, ff = i & 63;
        float s = ssum[i];
        unsigned m = smax[i];
        if (s != 0.f) atomicAdd(&g_pool_sum[(gmin + lg) * 64 + ff], s);
        if (m) atomicMax(&g_pool_max[(gmin + lg) * 64 + ff], m);
    }
    if (tid < ngr && scnt[tid]) atomicAdd(&g_pool_cnt[gmin + tid], scnt[tid]);
}

// ---------------- classifier: [mean|max|sum] @ cls_W + cls_b ----------------
__global__ void k_cls(const float* __restrict__ clsW, const float* __restrict__ clsb,
                      float* __restrict__ out) {
    int tid = threadIdx.x;
    if (tid >= GG * NCLS) return;
    int g = tid / 3, c = tid % 3;
    float cnt = fmaxf((float)g_pool_cnt[g], 1.f);
    float inv = 1.f / cnt;
    float acc = clsb[c];
    for (int ff = 0; ff < HH; ff++) {
        float s = g_pool_sum[g * 64 + ff];
        float m = __uint_as_float(g_pool_max[g * 64 + ff]);
        acc += (s * inv) * clsW[ff * 3 + c] + m * clsW[(64 + ff) * 3 + c] + s * clsW[(128 + ff) * 3 + c];
    }
    out[g * 3 + c] = acc;
}

// ---------------- launch ----------------
extern "C" void kernel_launch(void* const* d_in, const int* in_sizes, int n_in,
                              void* d_out, int out_size) {
    const float* x     = (const float*)d_in[0];
    const int*   ei    = (const int*)d_in[1];
    const int*   batch = (const int*)d_in[2];
    const float* W_exp = (const float*)d_in[3];
    const float* b_exp = (const float*)d_in[4];
    const float* gW1   = (const float*)d_in[5];
    const float* gb1   = (const float*)d_in[6];
    const float* gW2   = (const float*)d_in[7];
    const float* gb2   = (const float*)d_in[8];
    const float* W2    = (const float*)d_in[9];
    const float* b2    = (const float*)d_in[10];
    const float* bn1g  = (const float*)d_in[11];
    const float* bn1b  = (const float*)d_in[12];
    const float* bn2g  = (const float*)d_in[13];
    const float* bn2b  = (const float*)d_in[14];
    const float* clsW  = (const float*)d_in[15];
    const float* clsb  = (const float*)d_in[16];
    float* out = (float*)d_out;
    const int* src = ei;
    const int* dst = ei + EE;

    k_zero<<<(NN + 255) / 256, 256>>>();
    k_hist<<<(EE + 255) / 256, 256>>>(dst);
    k_scan<<<1, 1024>>>();
    k_fill<<<(EE + 255) / 256, 256>>>(src, dst);
    k_gate<<<592, 256>>>(x, gW1, gb1, gW2, gb2);
    k_prop1<<<(NN + 7) / 8, 256>>>(x);

    size_t smE = (size_t)(FIN * 192 + 192 + 16 * 4 * FIN) * sizeof(float);
    cudaFuncSetAttribute(k_expert, cudaFuncAttributeMaxDynamicSharedMemorySize, (int)smE);
    k_expert<<<148, 512, smE>>>(W_exp, b_exp);

    k_bnfin1<<<1, 64>>>(bn1g, bn1b);
    k_bnw2<<<592, 256>>>(W2);
    k_prop2<<<1184, 256>>>(b2);
    k_bnfin2<<<1, 64>>>(bn2g, bn2b);
    k_pool<<<(NN + 511) / 512, 256>>>(batch);
    k_cls<<<1, 192>>>(clsW, clsb, out);
}

// round 3
// speedup vs baseline: 1.0090x; 1.0090x over previous
#include <cuda_runtime.h>

#define NN   50000
#define EE   800000
#define FIN  128
#define HH   64
#define NEXP 3
#define GG   64
#define NCLS 3
#define BNEPS 1e-5f

typedef unsigned long long u64;

#define FMA2(acc, a, b) asm("fma.rn.f32x2 %0, %1, %2, %0;" : "+l"(acc) : "l"(a), "l"(b))

__device__ __forceinline__ float unpack_sum(u64 v) {
    float lo, hi;
    asm("mov.b64 {%0,%1}, %2;" : "=f"(lo), "=f"(hi) : "l"(v));
    return lo + hi;
}

// ---------------- static device scratch (no allocations) ----------------
__device__ int      g_deg_cnt[NN];
__device__ int      g_fill_cnt[NN];
__device__ int      g_row_ptr[NN + 1];
__device__ int      g_csr_src[EE];
__device__ float    g_disq[NN];
__device__ float    g_dinv[NN];
__device__ float    g_gate[NN * NEXP];
__device__ __align__(16) float g_xp[NN * FIN];
__device__ __align__(16) float g_h1[NN * HH];
__device__ __align__(16) float g_t[NN * HH];
__device__ __align__(16) float g_o2[NN * HH];
__device__ float    g_bn1_sum[HH], g_bn1_sq[HH];
__device__ float    g_bn2_sum[HH], g_bn2_sq[HH];
__device__ __align__(16) float g_sc1[HH];
__device__ __align__(16) float g_sh1[HH];
__device__ __align__(16) float g_sc2[HH];
__device__ __align__(16) float g_sh2[HH];
__device__ float    g_pool_sum[GG * HH];
__device__ unsigned g_pool_max[GG * HH];
__device__ int      g_pool_cnt[GG];

// ---------------- zero scratch ----------------
__global__ void k_zero() {
    int i = blockIdx.x * blockDim.x + threadIdx.x;
    if (i < NN) { g_deg_cnt[i] = 0; g_fill_cnt[i] = 0; }
    if (i < HH) { g_bn1_sum[i] = 0.f; g_bn1_sq[i] = 0.f; g_bn2_sum[i] = 0.f; g_bn2_sq[i] = 0.f; }
    if (i < GG * HH) { g_pool_sum[i] = 0.f; g_pool_max[i] = 0u; }
    if (i < GG) g_pool_cnt[i] = 0;
}

// ---------------- merged: in-degree histogram (blocks [0,HB)) + gate MLP ----------------
#define HIST_BLOCKS 3125
#define GATE_BLOCKS 592
__global__ void k_hist_gate(const int* __restrict__ dst,
                            const float* __restrict__ x, const float* __restrict__ W1,
                            const float* __restrict__ b1, const float* __restrict__ W2,
                            const float* __restrict__ b2g) {
    if (blockIdx.x < HIST_BLOCKS) {
        int e = blockIdx.x * blockDim.x + threadIdx.x;
        if (e < EE) atomicAdd(&g_deg_cnt[dst[e]], 1);
        return;
    }
    int bid = blockIdx.x - HIST_BLOCKS;
    __shared__ __align__(16) float2 W1s2[(FIN / 2) * 32];   // [f2][col]
    __shared__ float W2s[32 * 3];
    __shared__ float b1s[32];
    __shared__ float b2s[3];
    __shared__ __align__(16) float xs[8][4][FIN];
    int tid = threadIdx.x;
    for (int idx = tid; idx < (FIN / 2) * 32; idx += blockDim.x) {
        int f2 = idx >> 5, c = idx & 31;
        float2 v;
        v.x = W1[(2 * f2) * 32 + c];
        v.y = W1[(2 * f2 + 1) * 32 + c];
        W1s2[idx] = v;
    }
    if (tid < 96) W2s[tid] = W2[tid];
    if (tid < 32) b1s[tid] = b1[tid];
    if (tid < 3)  b2s[tid] = b2g[tid];
    __syncthreads();
    int w = tid >> 5, lane = tid & 31;
    int warps_total = GATE_BLOCKS * 8;
    for (int n0 = (bid * 8 + w) * 4; n0 < NN; n0 += warps_total * 4) {
        int nmax = min(4, NN - n0);
        for (int i = 0; i < nmax; i++) {
            float4 v = ((const float4*)(x + (size_t)(n0 + i) * FIN))[lane];
            ((float4*)&xs[w][i][0])[lane] = v;
        }
        __syncwarp();
        u64 acc2[4];
#pragma unroll
        for (int i = 0; i < 4; i++) acc2[i] = 0ull;
        for (int f2 = 0; f2 < FIN / 2; f2 += 2) {  // 4 features per iter
            ulonglong2 xp[4];
#pragma unroll
            for (int i = 0; i < 4; i++)
                xp[i] = *((const ulonglong2*)&xs[w][i][2 * f2]);
#pragma unroll
            for (int p = 0; p < 2; p++) {
                u64 wp = *((const u64*)&W1s2[(f2 + p) * 32 + lane]);
#pragma unroll
                for (int i = 0; i < 4; i++) {
                    u64 xpp = (p == 0) ? xp[i].x : xp[i].y;
                    FMA2(acc2[i], xpp, wp);
                }
            }
        }
        for (int i = 0; i < nmax; i++) {
            float hid = fmaxf(unpack_sum(acc2[i]) + b1s[lane], 0.f);
            float p0 = hid * W2s[lane * 3 + 0];
            float p1 = hid * W2s[lane * 3 + 1];
            float p2 = hid * W2s[lane * 3 + 2];
#pragma unroll
            for (int o = 16; o > 0; o >>= 1) {
                p0 += __shfl_down_sync(0xffffffffu, p0, o);
                p1 += __shfl_down_sync(0xffffffffu, p1, o);
                p2 += __shfl_down_sync(0xffffffffu, p2, o);
            }
            if (lane == 0) {
                p0 += b2s[0]; p1 += b2s[1]; p2 += b2s[2];
                float m = fmaxf(p0, fmaxf(p1, p2));
                float e0 = __expf(p0 - m), e1 = __expf(p1 - m), e2 = __expf(p2 - m);
                float inv = 1.f / (e0 + e1 + e2);
                int n = n0 + i;
                g_gate[n * 3 + 0] = e0 * inv;
                g_gate[n * 3 + 1] = e1 * inv;
                g_gate[n * 3 + 2] = e2 * inv;
            }
        }
        __syncwarp();
    }
}

// ---------------- exclusive scan (row_ptr) + deg_isqrt/deg_inv ----------------
__global__ void k_scan() {
    __shared__ int wsum[32];
    __shared__ int carry_s;
    const int tid = threadIdx.x, lane = tid & 31, wid = tid >> 5;
    if (tid == 0) carry_s = 0;
    __syncthreads();
    for (int base = 0; base < NN; base += 1024) {
        int i = base + tid;
        int v = (i < NN) ? g_deg_cnt[i] : 0;
        int x = v;
#pragma unroll
        for (int o = 1; o < 32; o <<= 1) {
            int y = __shfl_up_sync(0xffffffffu, x, o);
            if (lane >= o) x += y;
        }
        if (lane == 31) wsum[wid] = x;
        __syncthreads();
        if (wid == 0) {
            int w = wsum[lane];
#pragma unroll
            for (int o = 1; o < 32; o <<= 1) {
                int y = __shfl_up_sync(0xffffffffu, w, o);
                if (lane >= o) w += y;
            }
            wsum[lane] = w;
        }
        __syncthreads();
        int woff = (wid == 0) ? 0 : wsum[wid - 1];
        int incl = x + woff;
        int carry = carry_s;
        if (i < NN) {
            g_row_ptr[i] = carry + incl - v;
            float dg = (float)(v + 1);
            g_disq[i] = rsqrtf(dg);
            g_dinv[i] = 1.0f / dg;
        }
        __syncthreads();
        if (tid == 1023) carry_s = carry + incl;
        __syncthreads();
    }
    if (tid == 0) g_row_ptr[NN] = carry_s;
}

// ---------------- CSR fill ----------------
__global__ void k_fill(const int* __restrict__ src, const int* __restrict__ dst) {
    int e = blockIdx.x * blockDim.x + threadIdx.x;
    if (e < EE) {
        int d = dst[e];
        int pos = atomicAdd(&g_fill_cnt[d], 1);
        g_csr_src[g_row_ptr[d] + pos] = src[e];
    }
}

// ---------------- prop1: xp = GCN-prop(x), F=128, warp per dst node ----------------
__global__ void k_prop1(const float* __restrict__ x) {
    int w = (blockIdx.x * blockDim.x + threadIdx.x) >> 5;
    int lane = threadIdx.x & 31;
    if (w >= NN) return;
    int n = w;
    const float4* x4 = (const float4*)x;
    float4 a0 = make_float4(0.f, 0.f, 0.f, 0.f);
    float4 a1 = make_float4(0.f, 0.f, 0.f, 0.f);
    int j0 = g_row_ptr[n], j1 = g_row_ptr[n + 1];
    int j = j0;
    for (; j + 1 < j1; j += 2) {
        int s0 = __ldg(&g_csr_src[j]);
        int s1 = __ldg(&g_csr_src[j + 1]);
        float w0 = __ldg(&g_disq[s0]);
        float w1 = __ldg(&g_disq[s1]);
        float4 v0 = __ldg(&x4[(size_t)s0 * 32 + lane]);
        float4 v1 = __ldg(&x4[(size_t)s1 * 32 + lane]);
        a0.x += w0 * v0.x; a0.y += w0 * v0.y; a0.z += w0 * v0.z; a0.w += w0 * v0.w;
        a1.x += w1 * v1.x; a1.y += w1 * v1.y; a1.z += w1 * v1.z; a1.w += w1 * v1.w;
    }
    if (j < j1) {
        int s = __ldg(&g_csr_src[j]);
        float wv = __ldg(&g_disq[s]);
        float4 v = __ldg(&x4[(size_t)s * 32 + lane]);
        a0.x += wv * v.x; a0.y += wv * v.y; a0.z += wv * v.z; a0.w += wv * v.w;
    }
    float dq = g_disq[n], di = g_dinv[n];
    float4 sv = x4[(size_t)n * 32 + lane];
    float4 o;
    o.x = (a0.x + a1.x) * dq + sv.x * di;
    o.y = (a0.y + a1.y) * dq + sv.y * di;
    o.z = (a0.z + a1.z) * dq + sv.z * di;
    o.w = (a0.w + a1.w) * dq + sv.w * di;
    ((float4*)g_xp)[(size_t)n * 32 + lane] = o;
}

// ---------------- expert GEMM (f32x2) + bias + gate combine + BN1 partial stats ---------
// h1[n,h] = sum_e gate[n,e] * ( (xp @ W_e)[n,h] + b_exp[e,h] )
__global__ void __launch_bounds__(512, 1) k_expert(const float* __restrict__ W_exp,
                                                   const float* __restrict__ b_exp) {
    extern __shared__ __align__(16) float sm[];
    float2* Ws2 = (float2*)sm;                       // [FIN/2][192] feature pairs
    float*  be  = sm + (FIN / 2) * 192 * 2;          // [192]
    float*  xs  = be + 192;                          // [16 warps][4 nodes][FIN]
    int tid = threadIdx.x;
    for (int idx = tid; idx < (FIN / 2) * 192; idx += blockDim.x) {
        int f2 = idx / 192, c = idx % 192;
        int e = c >> 6, h = c & 63;
        float2 v;
        v.x = W_exp[((size_t)e * FIN + 2 * f2) * 64 + h];
        v.y = W_exp[((size_t)e * FIN + 2 * f2 + 1) * 64 + h];
        Ws2[idx] = v;
    }
    if (tid < 192) be[tid] = b_exp[tid];
    __syncthreads();
    int w = tid >> 5, lane = tid & 31;
    float* xw = xs + w * 4 * FIN;
    float bs0 = 0.f, bq0 = 0.f, bs1 = 0.f, bq1 = 0.f;
    int warps_total = gridDim.x * (blockDim.x >> 5);
    for (int n0 = (blockIdx.x * (blockDim.x >> 5) + w) * 4; n0 < NN; n0 += warps_total * 4) {
        int nmax = min(4, NN - n0);
        for (int i = 0; i < nmax; i++) {
            float4 v = ((const float4*)(g_xp + (size_t)(n0 + i) * FIN))[lane];
            ((float4*)(xw + i * FIN))[lane] = v;
        }
        __syncwarp();
        u64 acc2[4][6];
#pragma unroll
        for (int i = 0; i < 4; i++)
#pragma unroll
            for (int k = 0; k < 6; k++) acc2[i][k] = 0ull;
        for (int f2 = 0; f2 < FIN / 2; f2 += 2) {  // 4 features per iter
            ulonglong2 xp[4];
#pragma unroll
            for (int i = 0; i < 4; i++)
                xp[i] = *((const ulonglong2*)(xw + i * FIN + 2 * f2));
#pragma unroll
            for (int p = 0; p < 2; p++) {
                const float2* wrow = Ws2 + (f2 + p) * 192;
                u64 w0 = *((const u64*)&wrow[lane]);
                u64 w1 = *((const u64*)&wrow[lane + 32]);
                u64 w2 = *((const u64*)&wrow[lane + 64]);
                u64 w3 = *((const u64*)&wrow[lane + 96]);
                u64 w4 = *((const u64*)&wrow[lane + 128]);
                u64 w5 = *((const u64*)&wrow[lane + 160]);
#pragma unroll
                for (int i = 0; i < 4; i++) {
                    u64 xpp = (p == 0) ? xp[i].x : xp[i].y;
                    FMA2(acc2[i][0], xpp, w0);
                    FMA2(acc2[i][1], xpp, w1);
                    FMA2(acc2[i][2], xpp, w2);
                    FMA2(acc2[i][3], xpp, w3);
                    FMA2(acc2[i][4], xpp, w4);
                    FMA2(acc2[i][5], xpp, w5);
                }
            }
        }
        for (int i = 0; i < nmax; i++) {
            int n = n0 + i;
            float g0 = g_gate[n * 3 + 0], g1 = g_gate[n * 3 + 1], g2 = g_gate[n * 3 + 2];
            float a0 = unpack_sum(acc2[i][0]);
            float a1 = unpack_sum(acc2[i][1]);
            float a2 = unpack_sum(acc2[i][2]);
            float a3 = unpack_sum(acc2[i][3]);
            float a4 = unpack_sum(acc2[i][4]);
            float a5 = unpack_sum(acc2[i][5]);
            float oa = g0 * (a0 + be[lane]) + g1 * (a2 + be[64 + lane]) + g2 * (a4 + be[128 + lane]);
            float ob = g0 * (a1 + be[lane + 32]) + g1 * (a3 + be[96 + lane]) + g2 * (a5 + be[160 + lane]);
            g_h1[(size_t)n * 64 + lane] = oa;
            g_h1[(size_t)n * 64 + lane + 32] = ob;
            bs0 += oa; bq0 += oa * oa; bs1 += ob; bq1 += ob * ob;
        }
        __syncwarp();
    }
    atomicAdd(&g_bn1_sum[lane], bs0);
    atomicAdd(&g_bn1_sq[lane], bq0);
    atomicAdd(&g_bn1_sum[lane + 32], bs1);
    atomicAdd(&g_bn1_sq[lane + 32], bq1);
}

// ---------------- BN finalize ----------------
__global__ void k_bnfin1(const float* __restrict__ gam, const float* __restrict__ bet) {
    int i = threadIdx.x;
    if (i < HH) {
        float mu = g_bn1_sum[i] / (float)NN;
        float var = g_bn1_sq[i] / (float)NN - mu * mu;
        float sc = rsqrtf(var + BNEPS) * gam[i];
        g_sc1[i] = sc;
        g_sh1[i] = bet[i] - mu * sc;
    }
}
__global__ void k_bnfin2(const float* __restrict__ gam, const float* __restrict__ bet) {
    int i = threadIdx.x;
    if (i < HH) {
        float mu = g_bn2_sum[i] / (float)NN;
        float var = g_bn2_sq[i] / (float)NN - mu * mu;
        float sc = rsqrtf(var + BNEPS) * gam[i];
        g_sc2[i] = sc;
        g_sh2[i] = bet[i] - mu * sc;
    }
}

// ---------------- BN1 + ReLU + @W2 (f32x2) ----------------
__global__ void k_bnw2(const float* __restrict__ W2) {
    __shared__ __align__(16) float2 W2s2[(HH / 2) * HH];  // [f2][col]
    __shared__ __align__(16) float scs[HH];
    __shared__ __align__(16) float shs[HH];
    __shared__ __align__(16) float xs[8][4][HH];
    int tid = threadIdx.x;
    for (int idx = tid; idx < (HH / 2) * HH; idx += blockDim.x) {
        int f2 = idx >> 6, c = idx & 63;
        float2 v;
        v.x = W2[(2 * f2) * 64 + c];
        v.y = W2[(2 * f2 + 1) * 64 + c];
        W2s2[idx] = v;
    }
    if (tid < HH) { scs[tid] = g_sc1[tid]; shs[tid] = g_sh1[tid]; }
    __syncthreads();
    int w = tid >> 5, lane = tid & 31;
    int warps_total = gridDim.x * 8;
    for (int n0 = (blockIdx.x * 8 + w) * 4; n0 < NN; n0 += warps_total * 4) {
        int nmax = min(4, NN - n0);
        float2 sc = ((const float2*)scs)[lane];
        float2 sh = ((const float2*)shs)[lane];
        for (int i = 0; i < nmax; i++) {
            float2 v = ((const float2*)(g_h1 + (size_t)(n0 + i) * HH))[lane];
            float2 o;
            o.x = fmaxf(v.x * sc.x + sh.x, 0.f);
            o.y = fmaxf(v.y * sc.y + sh.y, 0.f);
            ((float2*)&xs[w][i][0])[lane] = o;
        }
        __syncwarp();
        u64 acc2[4][2];
#pragma unroll
        for (int i = 0; i < 4; i++) { acc2[i][0] = 0ull; acc2[i][1] = 0ull; }
        for (int f2 = 0; f2 < HH / 2; f2 += 2) {  // 4 features per iter
            ulonglong2 xp[4];
#pragma unroll
            for (int i = 0; i < 4; i++)
                xp[i] = *((const ulonglong2*)&xs[w][i][2 * f2]);
#pragma unroll
            for (int p = 0; p < 2; p++) {
                const float2* wrow = W2s2 + (f2 + p) * 64;
                u64 w0 = *((const u64*)&wrow[lane]);
                u64 w1 = *((const u64*)&wrow[lane + 32]);
#pragma unroll
                for (int i = 0; i < 4; i++) {
                    u64 xpp = (p == 0) ? xp[i].x : xp[i].y;
                    FMA2(acc2[i][0], xpp, w0);
                    FMA2(acc2[i][1], xpp, w1);
                }
            }
        }
        for (int i = 0; i < nmax; i++) {
            g_t[(size_t)(n0 + i) * 64 + lane] = unpack_sum(acc2[i][0]);
            g_t[(size_t)(n0 + i) * 64 + lane + 32] = unpack_sum(acc2[i][1]);
        }
        __syncwarp();
    }
}

// ---------------- prop2 (+b2) + BN2 partial stats ----------------
__global__ void k_prop2(const float* __restrict__ b2) {
    int lane = threadIdx.x & 31;
    int w = threadIdx.x >> 5;
    int warps_total = gridDim.x * (blockDim.x >> 5);
    const float2* t2 = (const float2*)g_t;
    float bsx = 0.f, bqx = 0.f, bsy = 0.f, bqy = 0.f;
    float2 bv;
    bv.x = b2[2 * lane];
    bv.y = b2[2 * lane + 1];
    for (int n = blockIdx.x * (blockDim.x >> 5) + w; n < NN; n += warps_total) {
        float2 a0 = make_float2(0.f, 0.f);
        float2 a1 = make_float2(0.f, 0.f);
        int j0 = g_row_ptr[n], j1 = g_row_ptr[n + 1];
        int j = j0;
        for (; j + 1 < j1; j += 2) {
            int s0 = __ldg(&g_csr_src[j]);
            int s1 = __ldg(&g_csr_src[j + 1]);
            float w0 = __ldg(&g_disq[s0]);
            float w1 = __ldg(&g_disq[s1]);
            float2 v0 = __ldg(&t2[(size_t)s0 * 32 + lane]);
            float2 v1 = __ldg(&t2[(size_t)s1 * 32 + lane]);
            a0.x += w0 * v0.x; a0.y += w0 * v0.y;
            a1.x += w1 * v1.x; a1.y += w1 * v1.y;
        }
        if (j < j1) {
            int s = __ldg(&g_csr_src[j]);
            float wv = __ldg(&g_disq[s]);
            float2 v = __ldg(&t2[(size_t)s * 32 + lane]);
            a0.x += wv * v.x; a0.y += wv * v.y;
        }
        float dq = g_disq[n], di = g_dinv[n];
        float2 sv = t2[(size_t)n * 32 + lane];
        float2 o;
        o.x = (a0.x + a1.x) * dq + sv.x * di + bv.x;
        o.y = (a0.y + a1.y) * dq + sv.y * di + bv.y;
        ((float2*)g_o2)[(size_t)n * 32 + lane] = o;
        bsx += o.x; bqx += o.x * o.x;
        bsy += o.y; bqy += o.y * o.y;
    }
    atomicAdd(&g_bn2_sum[2 * lane], bsx);
    atomicAdd(&g_bn2_sq[2 * lane], bqx);
    atomicAdd(&g_bn2_sum[2 * lane + 1], bsy);
    atomicAdd(&g_bn2_sq[2 * lane + 1], bqy);
}

// ---------------- BN2 + ReLU + segment pooling (sum/max/count) ----------------
__global__ void k_pool(const int* __restrict__ batch) {
    __shared__ float    ssum[GG * HH];
    __shared__ unsigned smax[GG * HH];
    __shared__ int      scnt[GG];
    int tid = threadIdx.x;
    int base = blockIdx.x * 512;
    int lastn = min(base + 511, NN - 1);
    int gmin = batch[base], gmax = batch[lastn];
    int ngr = gmax - gmin + 1;
    for (int i = tid; i < ngr * HH; i += blockDim.x) { ssum[i] = 0.f; smax[i] = 0u; }
    if (tid < ngr) scnt[tid] = 0;
    __syncthreads();
    int f = tid & 63, r = tid >> 6;
    float sc = g_sc2[f], sh = g_sh2[f];
    int curg = -1; float ls = 0.f, lm = 0.f; int lc = 0;
    for (int i = r; i < 512; i += 4) {
        int n = base + i;
        if (n >= NN) break;
        int g = batch[n];
        float v = fmaxf(g_o2[(size_t)n * 64 + f] * sc + sh, 0.f);
        if (g != curg) {
            if (curg >= 0) {
                atomicAdd(&ssum[(curg - gmin) * 64 + f], ls);
                atomicMax(&smax[(curg - gmin) * 64 + f], __float_as_uint(lm));
                if (f == 0) atomicAdd(&scnt[curg - gmin], lc);
            }
            curg = g; ls = v; lm = v; lc = 1;
        } else {
            ls += v; lm = fmaxf(lm, v); lc++;
        }
    }
    if (curg >= 0) {
        atomicAdd(&ssum[(curg - gmin) * 64 + f], ls);
        atomicMax(&smax[(curg - gmin) * 64 + f], __float_as_uint(lm));
        if (f == 0) atomicAdd(&scnt[curg - gmin], lc);
    }
    __syncthreads();
    for (int i = tid; i < ngr * HH; i += blockDim.x) {
        int lg = i >> 6, ff = i & 63;
        float s = ssum[i];
        unsigned m = smax[i];
        if (s != 0.f) atomicAdd(&g_pool_sum[(gmin + lg) * 64 + ff], s);
        if (m) atomicMax(&g_pool_max[(gmin + lg) * 64 + ff], m);
    }
    if (tid < ngr && scnt[tid]) atomicAdd(&g_pool_cnt[gmin + tid], scnt[tid]);
}

// ---------------- classifier ----------------
__global__ void k_cls(const float* __restrict__ clsW, const float* __restrict__ clsb,
                      float* __restrict__ out) {
    int tid = threadIdx.x;
    if (tid >= GG * NCLS) return;
    int g = tid / 3, c = tid % 3;
    float cnt = fmaxf((float)g_pool_cnt[g], 1.f);
    float inv = 1.f / cnt;
    float acc = clsb[c];
    for (int ff = 0; ff < HH; ff++) {
        float s = g_pool_sum[g * 64 + ff];
        float m = __uint_as_float(g_pool_max[g * 64 + ff]);
        acc += (s * inv) * clsW[ff * 3 + c] + m * clsW[(64 + ff) * 3 + c] + s * clsW[(128 + ff) * 3 + c];
    }
    out[g * 3 + c] = acc;
}

// ---------------- launch ----------------
extern "C" void kernel_launch(void* const* d_in, const int* in_sizes, int n_in,
                              void* d_out, int out_size) {
    const float* x     = (const float*)d_in[0];
    const int*   ei    = (const int*)d_in[1];
    const int*   batch = (const int*)d_in[2];
    const float* W_exp = (const float*)d_in[3];
    const float* b_exp = (const float*)d_in[4];
    const float* gW1   = (const float*)d_in[5];
    const float* gb1   = (const float*)d_in[6];
    const float* gW2   = (const float*)d_in[7];
    const float* gb2   = (const float*)d_in[8];
    const float* W2    = (const float*)d_in[9];
    const float* b2    = (const float*)d_in[10];
    const float* bn1g  = (const float*)d_in[11];
    const float* bn1b  = (const float*)d_in[12];
    const float* bn2g  = (const float*)d_in[13];
    const float* bn2b  = (const float*)d_in[14];
    const float* clsW  = (const float*)d_in[15];
    const float* clsb  = (const float*)d_in[16];
    float* out = (float*)d_out;
    const int* src = ei;
    const int* dst = ei + EE;

    k_zero<<<(NN + 255) / 256, 256>>>();
    k_hist_gate<<<HIST_BLOCKS + GATE_BLOCKS, 256>>>(dst, x, gW1, gb1, gW2, gb2);
    k_scan<<<1, 1024>>>();
    k_fill<<<(EE + 255) / 256, 256>>>(src, dst);
    k_prop1<<<(NN + 7) / 8, 256>>>(x);

    size_t smE = (size_t)(FIN / 2 * 192 * 2 + 192 + 16 * 4 * FIN) * sizeof(float);
    cudaFuncSetAttribute(k_expert, cudaFuncAttributeMaxDynamicSharedMemorySize, (int)smE);
    k_expert<<<148, 512, smE>>>(W_exp, b_exp);

    k_bnfin1<<<1, 64>>>(bn1g, bn1b);
    k_bnw2<<<592, 256>>>(W2);
    k_prop2<<<1184, 256>>>(b2);
    k_bnfin2<<<1, 64>>>(bn2g, bn2b);
    k_pool<<<(NN + 511) / 512, 256>>>(batch);
    k_cls<<<1, 192>>>(clsW, clsb, out);
}

// round 4
// speedup vs baseline: 1.1172x; 1.1072x over previous
#include <cuda_runtime.h>

#define NN   50000
#define EE   800000
#define FIN  128
#define HH   64
#define NEXP 3
#define GG   64
#define NCLS 3
#define BNEPS 1e-5f
#define SCAN_BLK 196   // ceil(50000/256)

typedef unsigned long long u64;

#define FMA2(acc, a, b) asm("fma.rn.f32x2 %0, %1, %2, %0;" : "+l"(acc) : "l"(a), "l"(b))

__device__ __forceinline__ float unpack_sum(u64 v) {
    float lo, hi;
    asm("mov.b64 {%0,%1}, %2;" : "=f"(lo), "=f"(hi) : "l"(v));
    return lo + hi;
}

// ---------------- static device scratch (no allocations) ----------------
__device__ int      g_deg_cnt[NN];
__device__ int      g_fill_cnt[NN];
__device__ int      g_row_ptr[NN + 1];
__device__ int      g_blk[SCAN_BLK];
__device__ int      g_blkoff[SCAN_BLK];
__device__ int      g_csr_src[EE];
__device__ float    g_disq[NN];
__device__ float    g_dinv[NN];
__device__ float    g_gate[NN * NEXP];
__device__ __align__(16) float g_xp[NN * FIN];
__device__ __align__(16) float g_h1[NN * HH];
__device__ __align__(16) float g_t[NN * HH];
__device__ __align__(16) float g_o2[NN * HH];
__device__ float    g_bn1_sum[HH], g_bn1_sq[HH];
__device__ float    g_bn2_sum[HH], g_bn2_sq[HH];
__device__ float    g_pool_sum[GG * HH];
__device__ unsigned g_pool_max[GG * HH];
__device__ int      g_pool_cnt[GG];

// ---------------- zero scratch ----------------
__global__ void k_zero() {
    int i = blockIdx.x * blockDim.x + threadIdx.x;
    if (i < NN) { g_deg_cnt[i] = 0; g_fill_cnt[i] = 0; }
    if (i < HH) { g_bn1_sum[i] = 0.f; g_bn1_sq[i] = 0.f; g_bn2_sum[i] = 0.f; g_bn2_sq[i] = 0.f; }
    if (i < GG * HH) { g_pool_sum[i] = 0.f; g_pool_max[i] = 0u; }
    if (i < GG) g_pool_cnt[i] = 0;
}

// ---------------- merged: in-degree histogram + gate MLP ----------------
#define HIST_BLOCKS 3125
#define GATE_BLOCKS 592
__global__ void k_hist_gate(const int* __restrict__ dst,
                            const float* __restrict__ x, const float* __restrict__ W1,
                            const float* __restrict__ b1, const float* __restrict__ W2,
                            const float* __restrict__ b2g) {
    if (blockIdx.x < HIST_BLOCKS) {
        int e = blockIdx.x * blockDim.x + threadIdx.x;
        if (e < EE) atomicAdd(&g_deg_cnt[dst[e]], 1);
        return;
    }
    int bid = blockIdx.x - HIST_BLOCKS;
    __shared__ __align__(16) float2 W1s2[(FIN / 2) * 32];   // [f2][col]
    __shared__ float W2s[32 * 3];
    __shared__ float b1s[32];
    __shared__ float b2s[3];
    __shared__ __align__(16) float xs[8][4][FIN];
    int tid = threadIdx.x;
    for (int idx = tid; idx < (FIN / 2) * 32; idx += blockDim.x) {
        int f2 = idx >> 5, c = idx & 31;
        float2 v;
        v.x = W1[(2 * f2) * 32 + c];
        v.y = W1[(2 * f2 + 1) * 32 + c];
        W1s2[idx] = v;
    }
    if (tid < 96) W2s[tid] = W2[tid];
    if (tid < 32) b1s[tid] = b1[tid];
    if (tid < 3)  b2s[tid] = b2g[tid];
    __syncthreads();
    int w = tid >> 5, lane = tid & 31;
    int warps_total = GATE_BLOCKS * 8;
    for (int n0 = (bid * 8 + w) * 4; n0 < NN; n0 += warps_total * 4) {
        int nmax = min(4, NN - n0);
        for (int i = 0; i < nmax; i++) {
            float4 v = ((const float4*)(x + (size_t)(n0 + i) * FIN))[lane];
            ((float4*)&xs[w][i][0])[lane] = v;
        }
        __syncwarp();
        u64 acc2[4];
#pragma unroll
        for (int i = 0; i < 4; i++) acc2[i] = 0ull;
        for (int f2 = 0; f2 < FIN / 2; f2 += 2) {
            ulonglong2 xp[4];
#pragma unroll
            for (int i = 0; i < 4; i++)
                xp[i] = *((const ulonglong2*)&xs[w][i][2 * f2]);
#pragma unroll
            for (int p = 0; p < 2; p++) {
                u64 wp = *((const u64*)&W1s2[(f2 + p) * 32 + lane]);
#pragma unroll
                for (int i = 0; i < 4; i++) {
                    u64 xpp = (p == 0) ? xp[i].x : xp[i].y;
                    FMA2(acc2[i], xpp, wp);
                }
            }
        }
        for (int i = 0; i < nmax; i++) {
            float hid = fmaxf(unpack_sum(acc2[i]) + b1s[lane], 0.f);
            float p0 = hid * W2s[lane * 3 + 0];
            float p1 = hid * W2s[lane * 3 + 1];
            float p2 = hid * W2s[lane * 3 + 2];
#pragma unroll
            for (int o = 16; o > 0; o >>= 1) {
                p0 += __shfl_down_sync(0xffffffffu, p0, o);
                p1 += __shfl_down_sync(0xffffffffu, p1, o);
                p2 += __shfl_down_sync(0xffffffffu, p2, o);
            }
            if (lane == 0) {
                p0 += b2s[0]; p1 += b2s[1]; p2 += b2s[2];
                float m = fmaxf(p0, fmaxf(p1, p2));
                float e0 = __expf(p0 - m), e1 = __expf(p1 - m), e2 = __expf(p2 - m);
                float inv = 1.f / (e0 + e1 + e2);
                int n = n0 + i;
                g_gate[n * 3 + 0] = e0 * inv;
                g_gate[n * 3 + 1] = e1 * inv;
                g_gate[n * 3 + 2] = e2 * inv;
            }
        }
        __syncwarp();
    }
}

// ---------------- parallel 3-phase scan ----------------
// phase 1: per-block local exclusive scan + block totals + disq/dinv
__global__ void k_scan1() {
    __shared__ int wsum[8];
    int tid = threadIdx.x, lane = tid & 31, wid = tid >> 5;
    int i = blockIdx.x * 256 + tid;
    int v = (i < NN) ? g_deg_cnt[i] : 0;
    int x = v;
#pragma unroll
    for (int o = 1; o < 32; o <<= 1) {
        int y = __shfl_up_sync(0xffffffffu, x, o);
        if (lane >= o) x += y;
    }
    if (lane == 31) wsum[wid] = x;
    __syncthreads();
    if (wid == 0 && lane < 8) {
        int t = wsum[lane];
#pragma unroll
        for (int o = 1; o < 8; o <<= 1) {
            int y = __shfl_up_sync(0xffu, t, o);
            if (lane >= o) t += y;
        }
        wsum[lane] = t;
    }
    __syncthreads();
    int woff = (wid == 0) ? 0 : wsum[wid - 1];
    if (i < NN) {
        g_row_ptr[i] = x - v + woff;   // local exclusive
        float dg = (float)(v + 1);
        g_disq[i] = rsqrtf(dg);
        g_dinv[i] = 1.0f / dg;
    }
    if (tid == 0) g_blk[blockIdx.x] = wsum[7];
}
// phase 2: scan the 196 block totals (1 block)
__global__ void k_scan2() {
    __shared__ int wsum[8];
    int tid = threadIdx.x, lane = tid & 31, wid = tid >> 5;
    int v = (tid < SCAN_BLK) ? g_blk[tid] : 0;
    int x = v;
#pragma unroll
    for (int o = 1; o < 32; o <<= 1) {
        int y = __shfl_up_sync(0xffffffffu, x, o);
        if (lane >= o) x += y;
    }
    if (lane == 31) wsum[wid] = x;
    __syncthreads();
    if (wid == 0 && lane < 8) {
        int t = wsum[lane];
#pragma unroll
        for (int o = 1; o < 8; o <<= 1) {
            int y = __shfl_up_sync(0xffu, t, o);
            if (lane >= o) t += y;
        }
        wsum[lane] = t;
    }
    __syncthreads();
    int woff = (wid == 0) ? 0 : wsum[wid - 1];
    if (tid < SCAN_BLK) g_blkoff[tid] = x - v + woff;  // exclusive
}
// phase 3: add block offsets; total is exactly EE
__global__ void k_scan3() {
    int i = blockIdx.x * 256 + threadIdx.x;
    if (i < NN) g_row_ptr[i] += g_blkoff[blockIdx.x];
    if (i == 0) g_row_ptr[NN] = EE;
}

// ---------------- CSR fill ----------------
__global__ void k_fill(const int* __restrict__ src, const int* __restrict__ dst) {
    int e = blockIdx.x * blockDim.x + threadIdx.x;
    if (e < EE) {
        int d = dst[e];
        int pos = atomicAdd(&g_fill_cnt[d], 1);
        g_csr_src[g_row_ptr[d] + pos] = src[e];
    }
}

// ---------------- prop1: xp = GCN-prop(x), F=128, warp per dst node ----------------
__global__ void k_prop1(const float* __restrict__ x) {
    int w = (blockIdx.x * blockDim.x + threadIdx.x) >> 5;
    int lane = threadIdx.x & 31;
    if (w >= NN) return;
    int n = w;
    const float4* x4 = (const float4*)x;
    float4 a0 = make_float4(0.f, 0.f, 0.f, 0.f);
    float4 a1 = make_float4(0.f, 0.f, 0.f, 0.f);
    int j0 = g_row_ptr[n], j1 = g_row_ptr[n + 1];
    int j = j0;
    for (; j + 1 < j1; j += 2) {
        int s0 = __ldg(&g_csr_src[j]);
        int s1 = __ldg(&g_csr_src[j + 1]);
        float w0 = __ldg(&g_disq[s0]);
        float w1 = __ldg(&g_disq[s1]);
        float4 v0 = __ldg(&x4[(size_t)s0 * 32 + lane]);
        float4 v1 = __ldg(&x4[(size_t)s1 * 32 + lane]);
        a0.x += w0 * v0.x; a0.y += w0 * v0.y; a0.z += w0 * v0.z; a0.w += w0 * v0.w;
        a1.x += w1 * v1.x; a1.y += w1 * v1.y; a1.z += w1 * v1.z; a1.w += w1 * v1.w;
    }
    if (j < j1) {
        int s = __ldg(&g_csr_src[j]);
        float wv = __ldg(&g_disq[s]);
        float4 v = __ldg(&x4[(size_t)s * 32 + lane]);
        a0.x += wv * v.x; a0.y += wv * v.y; a0.z += wv * v.z; a0.w += wv * v.w;
    }
    float dq = g_disq[n], di = g_dinv[n];
    float4 sv = x4[(size_t)n * 32 + lane];
    float4 o;
    o.x = (a0.x + a1.x) * dq + sv.x * di;
    o.y = (a0.y + a1.y) * dq + sv.y * di;
    o.z = (a0.z + a1.z) * dq + sv.z * di;
    o.w = (a0.w + a1.w) * dq + sv.w * di;
    ((float4*)g_xp)[(size_t)n * 32 + lane] = o;
}

// ---------------- expert GEMM (f32x2) + bias + gate combine + BN1 partial stats ---------
__global__ void __launch_bounds__(512, 1) k_expert(const float* __restrict__ W_exp,
                                                   const float* __restrict__ b_exp) {
    extern __shared__ __align__(16) float sm[];
    float2* Ws2 = (float2*)sm;                       // [FIN/2][192] feature pairs
    float*  be  = sm + (FIN / 2) * 192 * 2;          // [192]
    float*  xs  = be + 192;                          // [16 warps][4 nodes][FIN]
    int tid = threadIdx.x;
    for (int idx = tid; idx < (FIN / 2) * 192; idx += blockDim.x) {
        int f2 = idx / 192, c = idx % 192;
        int e = c >> 6, h = c & 63;
        float2 v;
        v.x = W_exp[((size_t)e * FIN + 2 * f2) * 64 + h];
        v.y = W_exp[((size_t)e * FIN + 2 * f2 + 1) * 64 + h];
        Ws2[idx] = v;
    }
    if (tid < 192) be[tid] = b_exp[tid];
    __syncthreads();
    int w = tid >> 5, lane = tid & 31;
    float* xw = xs + w * 4 * FIN;
    float bs0 = 0.f, bq0 = 0.f, bs1 = 0.f, bq1 = 0.f;
    int warps_total = gridDim.x * (blockDim.x >> 5);
    for (int n0 = (blockIdx.x * (blockDim.x >> 5) + w) * 4; n0 < NN; n0 += warps_total * 4) {
        int nmax = min(4, NN - n0);
        for (int i = 0; i < nmax; i++) {
            float4 v = ((const float4*)(g_xp + (size_t)(n0 + i) * FIN))[lane];
            ((float4*)(xw + i * FIN))[lane] = v;
        }
        __syncwarp();
        u64 acc2[4][6];
#pragma unroll
        for (int i = 0; i < 4; i++)
#pragma unroll
            for (int k = 0; k < 6; k++) acc2[i][k] = 0ull;
        for (int f2 = 0; f2 < FIN / 2; f2 += 2) {
            ulonglong2 xp[4];
#pragma unroll
            for (int i = 0; i < 4; i++)
                xp[i] = *((const ulonglong2*)(xw + i * FIN + 2 * f2));
#pragma unroll
            for (int p = 0; p < 2; p++) {
                const float2* wrow = Ws2 + (f2 + p) * 192;
                u64 w0 = *((const u64*)&wrow[lane]);
                u64 w1 = *((const u64*)&wrow[lane + 32]);
                u64 w2 = *((const u64*)&wrow[lane + 64]);
                u64 w3 = *((const u64*)&wrow[lane + 96]);
                u64 w4 = *((const u64*)&wrow[lane + 128]);
                u64 w5 = *((const u64*)&wrow[lane + 160]);
#pragma unroll
                for (int i = 0; i < 4; i++) {
                    u64 xpp = (p == 0) ? xp[i].x : xp[i].y;
                    FMA2(acc2[i][0], xpp, w0);
                    FMA2(acc2[i][1], xpp, w1);
                    FMA2(acc2[i][2], xpp, w2);
                    FMA2(acc2[i][3], xpp, w3);
                    FMA2(acc2[i][4], xpp, w4);
                    FMA2(acc2[i][5], xpp, w5);
                }
            }
        }
        for (int i = 0; i < nmax; i++) {
            int n = n0 + i;
            float g0 = g_gate[n * 3 + 0], g1 = g_gate[n * 3 + 1], g2 = g_gate[n * 3 + 2];
            float a0 = unpack_sum(acc2[i][0]);
            float a1 = unpack_sum(acc2[i][1]);
            float a2 = unpack_sum(acc2[i][2]);
            float a3 = unpack_sum(acc2[i][3]);
            float a4 = unpack_sum(acc2[i][4]);
            float a5 = unpack_sum(acc2[i][5]);
            float oa = g0 * (a0 + be[lane]) + g1 * (a2 + be[64 + lane]) + g2 * (a4 + be[128 + lane]);
            float ob = g0 * (a1 + be[lane + 32]) + g1 * (a3 + be[96 + lane]) + g2 * (a5 + be[160 + lane]);
            g_h1[(size_t)n * 64 + lane] = oa;
            g_h1[(size_t)n * 64 + lane + 32] = ob;
            bs0 += oa; bq0 += oa * oa; bs1 += ob; bq1 += ob * ob;
        }
        __syncwarp();
    }
    atomicAdd(&g_bn1_sum[lane], bs0);
    atomicAdd(&g_bn1_sq[lane], bq0);
    atomicAdd(&g_bn1_sum[lane + 32], bs1);
    atomicAdd(&g_bn1_sq[lane + 32], bq1);
}

// ---------------- BN1 + ReLU + @W2 (f32x2); BN finalize folded in ----------------
__global__ void k_bnw2(const float* __restrict__ W2,
                       const float* __restrict__ gam, const float* __restrict__ bet) {
    __shared__ __align__(16) float2 W2s2[(HH / 2) * HH];  // [f2][col]
    __shared__ __align__(16) float scs[HH];
    __shared__ __align__(16) float shs[HH];
    __shared__ __align__(16) float xs[8][4][HH];
    int tid = threadIdx.x;
    for (int idx = tid; idx < (HH / 2) * HH; idx += blockDim.x) {
        int f2 = idx >> 6, c = idx & 63;
        float2 v;
        v.x = W2[(2 * f2) * 64 + c];
        v.y = W2[(2 * f2 + 1) * 64 + c];
        W2s2[idx] = v;
    }
    if (tid < HH) {
        float mu = g_bn1_sum[tid] / (float)NN;
        float var = g_bn1_sq[tid] / (float)NN - mu * mu;
        float sc = rsqrtf(var + BNEPS) * gam[tid];
        scs[tid] = sc;
        shs[tid] = bet[tid] - mu * sc;
    }
    __syncthreads();
    int w = tid >> 5, lane = tid & 31;
    int warps_total = gridDim.x * 8;
    for (int n0 = (blockIdx.x * 8 + w) * 4; n0 < NN; n0 += warps_total * 4) {
        int nmax = min(4, NN - n0);
        float2 sc = ((const float2*)scs)[lane];
        float2 sh = ((const float2*)shs)[lane];
        for (int i = 0; i < nmax; i++) {
            float2 v = ((const float2*)(g_h1 + (size_t)(n0 + i) * HH))[lane];
            float2 o;
            o.x = fmaxf(v.x * sc.x + sh.x, 0.f);
            o.y = fmaxf(v.y * sc.y + sh.y, 0.f);
            ((float2*)&xs[w][i][0])[lane] = o;
        }
        __syncwarp();
        u64 acc2[4][2];
#pragma unroll
        for (int i = 0; i < 4; i++) { acc2[i][0] = 0ull; acc2[i][1] = 0ull; }
        for (int f2 = 0; f2 < HH / 2; f2 += 2) {
            ulonglong2 xp[4];
#pragma unroll
            for (int i = 0; i < 4; i++)
                xp[i] = *((const ulonglong2*)&xs[w][i][2 * f2]);
#pragma unroll
            for (int p = 0; p < 2; p++) {
                const float2* wrow = W2s2 + (f2 + p) * 64;
                u64 w0 = *((const u64*)&wrow[lane]);
                u64 w1 = *((const u64*)&wrow[lane + 32]);
#pragma unroll
                for (int i = 0; i < 4; i++) {
                    u64 xpp = (p == 0) ? xp[i].x : xp[i].y;
                    FMA2(acc2[i][0], xpp, w0);
                    FMA2(acc2[i][1], xpp, w1);
                }
            }
        }
        for (int i = 0; i < nmax; i++) {
            g_t[(size_t)(n0 + i) * 64 + lane] = unpack_sum(acc2[i][0]);
            g_t[(size_t)(n0 + i) * 64 + lane + 32] = unpack_sum(acc2[i][1]);
        }
        __syncwarp();
    }
}

// ---------------- prop2 (+b2) + BN2 partial stats ----------------
__global__ void k_prop2(const float* __restrict__ b2) {
    int lane = threadIdx.x & 31;
    int w = threadIdx.x >> 5;
    int warps_total = gridDim.x * (blockDim.x >> 5);
    const float2* t2 = (const float2*)g_t;
    float bsx = 0.f, bqx = 0.f, bsy = 0.f, bqy = 0.f;
    float2 bv;
    bv.x = b2[2 * lane];
    bv.y = b2[2 * lane + 1];
    for (int n = blockIdx.x * (blockDim.x >> 5) + w; n < NN; n += warps_total) {
        float2 a0 = make_float2(0.f, 0.f);
        float2 a1 = make_float2(0.f, 0.f);
        int j0 = g_row_ptr[n], j1 = g_row_ptr[n + 1];
        int j = j0;
        for (; j + 1 < j1; j += 2) {
            int s0 = __ldg(&g_csr_src[j]);
            int s1 = __ldg(&g_csr_src[j + 1]);
            float w0 = __ldg(&g_disq[s0]);
            float w1 = __ldg(&g_disq[s1]);
            float2 v0 = __ldg(&t2[(size_t)s0 * 32 + lane]);
            float2 v1 = __ldg(&t2[(size_t)s1 * 32 + lane]);
            a0.x += w0 * v0.x; a0.y += w0 * v0.y;
            a1.x += w1 * v1.x; a1.y += w1 * v1.y;
        }
        if (j < j1) {
            int s = __ldg(&g_csr_src[j]);
            float wv = __ldg(&g_disq[s]);
            float2 v = __ldg(&t2[(size_t)s * 32 + lane]);
            a0.x += wv * v.x; a0.y += wv * v.y;
        }
        float dq = g_disq[n], di = g_dinv[n];
        float2 sv = t2[(size_t)n * 32 + lane];
        float2 o;
        o.x = (a0.x + a1.x) * dq + sv.x * di + bv.x;
        o.y = (a0.y + a1.y) * dq + sv.y * di + bv.y;
        ((float2*)g_o2)[(size_t)n * 32 + lane] = o;
        bsx += o.x; bqx += o.x * o.x;
        bsy += o.y; bqy += o.y * o.y;
    }
    atomicAdd(&g_bn2_sum[2 * lane], bsx);
    atomicAdd(&g_bn2_sq[2 * lane], bqx);
    atomicAdd(&g_bn2_sum[2 * lane + 1], bsy);
    atomicAdd(&g_bn2_sq[2 * lane + 1], bqy);
}

// ---------------- BN2 + ReLU + segment pooling; BN finalize folded in ----------------
__global__ void k_pool(const int* __restrict__ batch,
                       const float* __restrict__ gam, const float* __restrict__ bet) {
    __shared__ float    ssum[GG * HH];
    __shared__ unsigned smax[GG * HH];
    __shared__ int      scnt[GG];
    __shared__ float    sc2s[HH], sh2s[HH];
    int tid = threadIdx.x;
    int base = blockIdx.x * 512;
    int lastn = min(base + 511, NN - 1);
    int gmin = batch[base], gmax = batch[lastn];
    int ngr = gmax - gmin + 1;
    for (int i = tid; i < ngr * HH; i += blockDim.x) { ssum[i] = 0.f; smax[i] = 0u; }
    if (tid < ngr) scnt[tid] = 0;
    if (tid < HH) {
        float mu = g_bn2_sum[tid] / (float)NN;
        float var = g_bn2_sq[tid] / (float)NN - mu * mu;
        float sc = rsqrtf(var + BNEPS) * gam[tid];
        sc2s[tid] = sc;
        sh2s[tid] = bet[tid] - mu * sc;
    }
    __syncthreads();
    int f = tid & 63, r = tid >> 6;
    float sc = sc2s[f], sh = sh2s[f];
    int curg = -1; float ls = 0.f, lm = 0.f; int lc = 0;
    for (int i = r; i < 512; i += 4) {
        int n = base + i;
        if (n >= NN) break;
        int g = batch[n];
        float v = fmaxf(g_o2[(size_t)n * 64 + f] * sc + sh, 0.f);
        if (g != curg) {
            if (curg >= 0) {
                atomicAdd(&ssum[(curg - gmin) * 64 + f], ls);
                atomicMax(&smax[(curg - gmin) * 64 + f], __float_as_uint(lm));
                if (f == 0) atomicAdd(&scnt[curg - gmin], lc);
            }
            curg = g; ls = v; lm = v; lc = 1;
        } else {
            ls += v; lm = fmaxf(lm, v); lc++;
        }
    }
    if (curg >= 0) {
        atomicAdd(&ssum[(curg - gmin) * 64 + f], ls);
        atomicMax(&smax[(curg - gmin) * 64 + f], __float_as_uint(lm));
        if (f == 0) atomicAdd(&scnt[curg - gmin], lc);
    }
    __syncthreads();
    for (int i = tid; i < ngr * HH; i += blockDim.x) {
        int lg = i >> 6, ff = i & 63;
        float s = ssum[i];
        unsigned m = smax[i];
        if (s != 0.f) atomicAdd(&g_pool_sum[(gmin + lg) * 64 + ff], s);
        if (m) atomicMax(&g_pool_max[(gmin + lg) * 64 + ff], m);
    }
    if (tid < ngr && scnt[tid]) atomicAdd(&g_pool_cnt[gmin + tid], scnt[tid]);
}

// ---------------- classifier ----------------
__global__ void k_cls(const float* __restrict__ clsW, const float* __restrict__ clsb,
                      float* __restrict__ out) {
    int tid = threadIdx.x;
    if (tid >= GG * NCLS) return;
    int g = tid / 3, c = tid % 3;
    float cnt = fmaxf((float)g_pool_cnt[g], 1.f);
    float inv = 1.f / cnt;
    float acc = clsb[c];
    for (int ff = 0; ff < HH; ff++) {
        float s = g_pool_sum[g * 64 + ff];
        float m = __uint_as_float(g_pool_max[g * 64 + ff]);
        acc += (s * inv) * clsW[ff * 3 + c] + m * clsW[(64 + ff) * 3 + c] + s * clsW[(128 + ff) * 3 + c];
    }
    out[g * 3 + c] = acc;
}

// ---------------- launch ----------------
extern "C" void kernel_launch(void* const* d_in, const int* in_sizes, int n_in,
                              void* d_out, int out_size) {
    const float* x     = (const float*)d_in[0];
    const int*   ei    = (const int*)d_in[1];
    const int*   batch = (const int*)d_in[2];
    const float* W_exp = (const float*)d_in[3];
    const float* b_exp = (const float*)d_in[4];
    const float* gW1   = (const float*)d_in[5];
    const float* gb1   = (const float*)d_in[6];
    const float* gW2   = (const float*)d_in[7];
    const float* gb2   = (const float*)d_in[8];
    const float* W2    = (const float*)d_in[9];
    const float* b2    = (const float*)d_in[10];
    const float* bn1g  = (const float*)d_in[11];
    const float* bn1b  = (const float*)d_in[12];
    const float* bn2g  = (const float*)d_in[13];
    const float* bn2b  = (const float*)d_in[14];
    const float* clsW  = (const float*)d_in[15];
    const float* clsb  = (const float*)d_in[16];
    float* out = (float*)d_out;
    const int* src = ei;
    const int* dst = ei + EE;

    k_zero<<<(NN + 255) / 256, 256>>>();
    k_hist_gate<<<HIST_BLOCKS + GATE_BLOCKS, 256>>>(dst, x, gW1, gb1, gW2, gb2);
    k_scan1<<<SCAN_BLK, 256>>>();
    k_scan2<<<1, 256>>>();
    k_scan3<<<SCAN_BLK, 256>>>();
    k_fill<<<(EE + 255) / 256, 256>>>(src, dst);
    k_prop1<<<(NN + 7) / 8, 256>>>(x);

    size_t smE = (size_t)(FIN / 2 * 192 * 2 + 192 + 16 * 4 * FIN) * sizeof(float);
    cudaFuncSetAttribute(k_expert, cudaFuncAttributeMaxDynamicSharedMemorySize, (int)smE);
    k_expert<<<148, 512, smE>>>(W_exp, b_exp);

    k_bnw2<<<592, 256>>>(W2, bn1g, bn1b);
    k_prop2<<<1184, 256>>>(b2);
    k_pool<<<(NN + 511) / 512, 256>>>(batch, bn2g, bn2b);
    k_cls<<<1, 192>>>(clsW, clsb, out);
}